// round 16
// baseline (speedup 1.0000x reference)
#include <cuda_runtime.h>

// ---------------------------------------------------------------------------
// Pin2PinAttraction: out = sum_j w[j] * ((x[a_j]-x[b_j])^2 + (y[a_j]-y[b_j])^2)
// R13 configuration (session best 72.2us) with ONE change: the attraction grid
// is sized to its true residency (40 regs -> 6 CTAs/SM -> 888 blocks), making
// it a single co-resident wave instead of 888 + 296-block straggler wave.
//   K1: pack (x,y)->float2 scratch via 128-bit stores; __ldcs streaming reads;
//       block 0 detects pairs dtype (1K words, single pass) + resets.
//   K2: gather+reduce (4x unrolled, __ldcs streams, natural 40 regs);
//       last block writes d_out.
// ---------------------------------------------------------------------------

#define MAX_PINS 2000000
#define NBLOCKS  888           // 6 CTAs per SM x 148 SMs — one wave at 40 regs
#define NTHREADS 256

__device__ float2       g_xy[MAX_PINS];   // 16 MB static scratch — legal
__device__ double       g_sum;
__device__ unsigned int g_count;
__device__ int          g_is64;

// --- Kernel 1: pack x,y into float2; block 0 detects dtype + resets ---------
__global__ void __launch_bounds__(NTHREADS)
pack_kernel(const float* __restrict__ pin_pos, int num_pins,
            const int* __restrict__ pairs32) {
    // int64 pairs (>=0, < 2^31, LE) have zero high words at word indices
    // 4i+1, 4i+3. int32 pairs put b-indices there — 2K uniform samples in
    // [0,2M) are essentially never all zero. Single pass: 256 threads x 2
    // sampled word-pairs.
    if (blockIdx.x == 0) {
        __shared__ int s_nz[NTHREADS];
        int t = threadIdx.x;
        int nz = pairs32[4 * t + 1] | pairs32[4 * t + 3]
               | pairs32[4 * (t + NTHREADS) + 1]
               | pairs32[4 * (t + NTHREADS) + 3];
        s_nz[t] = nz;
        __syncthreads();
        for (int s = NTHREADS / 2; s > 0; s >>= 1) {
            if (t < s) s_nz[t] |= s_nz[t + s];
            __syncthreads();
        }
        if (t == 0) {
            g_is64  = (s_nz[0] == 0) ? 1 : 0;
            g_sum   = 0.0;
            g_count = 0u;
        }
    }

    // Streaming reads (read-once): keep L2 clean for the g_xy gather lines.
    // Stores: 2x STG.128 per thread (32 contiguous bytes).
    const float4* __restrict__ xs4 = (const float4*)pin_pos;
    const float4* __restrict__ ys4 = (const float4*)(pin_pos + num_pins);
    float4* __restrict__ xy4 = (float4*)g_xy;   // g_xy is 16B-aligned (global)
    int n4 = num_pins >> 2;
    int stride = gridDim.x * blockDim.x;
    for (int i = blockIdx.x * blockDim.x + threadIdx.x; i < n4; i += stride) {
        float4 x = __ldcs(&xs4[i]);
        float4 y = __ldcs(&ys4[i]);
        xy4[2 * i + 0] = make_float4(x.x, y.x, x.y, y.y);
        xy4[2 * i + 1] = make_float4(x.z, y.z, x.w, y.w);
    }
    for (int i = (n4 << 2) + blockIdx.x * blockDim.x + threadIdx.x;
         i < num_pins; i += stride)
        g_xy[i] = make_float2(__ldcs(&pin_pos[i]),
                              __ldcs(&pin_pos[num_pins + i]));
}

// --- Kernel 2: main gather + reduce + last-block writeout --------------------
// Natural register allocation (40 regs — R14 showed capping serializes the
// 4x load batch). Grid sized to residency: one co-resident wave.
__global__ void __launch_bounds__(NTHREADS)
attraction_kernel(const void* __restrict__ pairs_raw,
                  const float* __restrict__ weights,
                  int num_pairs,
                  float* __restrict__ out) {
    const int is64 = g_is64;
    const int tid    = blockIdx.x * blockDim.x + threadIdx.x;
    const int stride = gridDim.x * blockDim.x;

    float acc0 = 0.0f, acc1 = 0.0f, acc2 = 0.0f, acc3 = 0.0f;

    if (is64) {
        const int4* __restrict__ p4 = (const int4*)pairs_raw;
        int j = tid;
        for (; j + 3 * stride < num_pairs; j += 4 * stride) {
            int4  pA = __ldcs(&p4[j]);
            int4  pB = __ldcs(&p4[j +     stride]);
            int4  pC = __ldcs(&p4[j + 2 * stride]);
            int4  pD = __ldcs(&p4[j + 3 * stride]);
            float wA = __ldcs(&weights[j]);
            float wB = __ldcs(&weights[j +     stride]);
            float wC = __ldcs(&weights[j + 2 * stride]);
            float wD = __ldcs(&weights[j + 3 * stride]);
            float2 a0 = __ldg(&g_xy[pA.x]);
            float2 b0 = __ldg(&g_xy[pA.z]);
            float2 a1 = __ldg(&g_xy[pB.x]);
            float2 b1 = __ldg(&g_xy[pB.z]);
            float2 a2 = __ldg(&g_xy[pC.x]);
            float2 b2 = __ldg(&g_xy[pC.z]);
            float2 a3 = __ldg(&g_xy[pD.x]);
            float2 b3 = __ldg(&g_xy[pD.z]);
            float dx0 = a0.x - b0.x, dy0 = a0.y - b0.y;
            float dx1 = a1.x - b1.x, dy1 = a1.y - b1.y;
            float dx2 = a2.x - b2.x, dy2 = a2.y - b2.y;
            float dx3 = a3.x - b3.x, dy3 = a3.y - b3.y;
            acc0 = fmaf(wA, fmaf(dx0, dx0, dy0 * dy0), acc0);
            acc1 = fmaf(wB, fmaf(dx1, dx1, dy1 * dy1), acc1);
            acc2 = fmaf(wC, fmaf(dx2, dx2, dy2 * dy2), acc2);
            acc3 = fmaf(wD, fmaf(dx3, dx3, dy3 * dy3), acc3);
        }
        for (; j < num_pairs; j += stride) {
            int4  p = __ldcs(&p4[j]);
            float w = __ldcs(&weights[j]);
            float2 a = __ldg(&g_xy[p.x]);
            float2 b = __ldg(&g_xy[p.z]);
            float dx = a.x - b.x, dy = a.y - b.y;
            acc0 = fmaf(w, fmaf(dx, dx, dy * dy), acc0);
        }
    } else {
        const int2* __restrict__ p2 = (const int2*)pairs_raw;
        int j = tid;
        for (; j + 3 * stride < num_pairs; j += 4 * stride) {
            int2  pA = __ldcs(&p2[j]);
            int2  pB = __ldcs(&p2[j +     stride]);
            int2  pC = __ldcs(&p2[j + 2 * stride]);
            int2  pD = __ldcs(&p2[j + 3 * stride]);
            float wA = __ldcs(&weights[j]);
            float wB = __ldcs(&weights[j +     stride]);
            float wC = __ldcs(&weights[j + 2 * stride]);
            float wD = __ldcs(&weights[j + 3 * stride]);
            float2 a0 = __ldg(&g_xy[pA.x]);
            float2 b0 = __ldg(&g_xy[pA.y]);
            float2 a1 = __ldg(&g_xy[pB.x]);
            float2 b1 = __ldg(&g_xy[pB.y]);
            float2 a2 = __ldg(&g_xy[pC.x]);
            float2 b2 = __ldg(&g_xy[pC.y]);
            float2 a3 = __ldg(&g_xy[pD.x]);
            float2 b3 = __ldg(&g_xy[pD.y]);
            float dx0 = a0.x - b0.x, dy0 = a0.y - b0.y;
            float dx1 = a1.x - b1.x, dy1 = a1.y - b1.y;
            float dx2 = a2.x - b2.x, dy2 = a2.y - b2.y;
            float dx3 = a3.x - b3.x, dy3 = a3.y - b3.y;
            acc0 = fmaf(wA, fmaf(dx0, dx0, dy0 * dy0), acc0);
            acc1 = fmaf(wB, fmaf(dx1, dx1, dy1 * dy1), acc1);
            acc2 = fmaf(wC, fmaf(dx2, dx2, dy2 * dy2), acc2);
            acc3 = fmaf(wD, fmaf(dx3, dx3, dy3 * dy3), acc3);
        }
        for (; j < num_pairs; j += stride) {
            int2  p = __ldcs(&p2[j]);
            float w = __ldcs(&weights[j]);
            float2 a = __ldg(&g_xy[p.x]);
            float2 b = __ldg(&g_xy[p.y]);
            float dx = a.x - b.x, dy = a.y - b.y;
            acc0 = fmaf(w, fmaf(dx, dx, dy * dy), acc0);
        }
    }

    float acc = (acc0 + acc1) + (acc2 + acc3);

    // warp reduce
    #pragma unroll
    for (int off = 16; off > 0; off >>= 1)
        acc += __shfl_xor_sync(0xFFFFFFFFu, acc, off);

    __shared__ float s_warp[NTHREADS / 32];
    int lane = threadIdx.x & 31;
    int wid  = threadIdx.x >> 5;
    if (lane == 0) s_warp[wid] = acc;
    __syncthreads();

    if (threadIdx.x == 0) {
        double blk = 0.0;
        #pragma unroll
        for (int w = 0; w < NTHREADS / 32; w++) blk += (double)s_warp[w];
        atomicAdd(&g_sum, blk);
        __threadfence();
        unsigned int done = atomicAdd(&g_count, 1u);
        if (done == gridDim.x - 1) {
            __threadfence();
            out[0] = (float)g_sum;
        }
    }
}

extern "C" void kernel_launch(void* const* d_in, const int* in_sizes, int n_in,
                              void* d_out, int out_size) {
    const float* pin_pos = (const float*)d_in[0];
    const float* weights = (const float*)d_in[1];
    const void*  pairs   = d_in[2];
    // d_in[3] = pin_mask (unused by reference)

    int num_pins  = in_sizes[0] / 2;
    int num_pairs = in_sizes[1];

    // One float4 per thread (balanced one-shot layout; R10/R12/R13-proven).
    int pack_blocks = ((num_pins >> 2) + NTHREADS - 1) / NTHREADS;
    if (pack_blocks > 2048) pack_blocks = 2048;
    if (pack_blocks < 1)    pack_blocks = 1;
    pack_kernel<<<pack_blocks, NTHREADS>>>(pin_pos, num_pins, (const int*)pairs);

    attraction_kernel<<<NBLOCKS, NTHREADS>>>(pairs, weights, num_pairs,
                                             (float*)d_out);
}